// round 13
// baseline (speedup 1.0000x reference)
#include <cuda_runtime.h>
#include <math.h>
#include <stdint.h>

// Problem constants
#define S_LEN   256
#define B_SZ    64
#define E_DIM   300
#define H2_DIM  256
#define H_DIM   512
#define T_TAGS  10
#define START_TAG 8
#define STOP_TAG  9
#define NTOK    (S_LEN * B_SZ)     // 16384
#define G4      (4 * H2_DIM)       // 1024

#define LSTM_BLOCKS 128
#define GROUP_BLOCKS 32            // blocks per (dir, batch-half) barrier group

typedef unsigned long long ull;

// ---------- packed f32x2 helpers (exact fp32, 2x FMA-pipe throughput) ------
__device__ __forceinline__ ull pk2(float x, float y) {
    ull r;
    asm("mov.b64 %0, {%1, %2};" : "=l"(r) : "f"(x), "f"(y));
    return r;
}
__device__ __forceinline__ void fma2(ull& c, ull a, ull b) {
    asm("fma.rn.f32x2 %0, %1, %2, %0;" : "+l"(c) : "l"(a), "l"(b));
}
__device__ __forceinline__ float2 up2(ull v) {
    float2 r;
    asm("mov.b64 {%0, %1}, %2;" : "=f"(r.x), "=f"(r.y) : "l"(v));
    return r;
}

// ---------------- scratch (device globals; no allocation allowed) ----------
__device__ __align__(16) float d_G[2][NTOK][G4];        // gate preactivations (x part + biases)
__device__ __align__(16) float d_Hout[NTOK][H_DIM];     // concatenated hidden states (S*B, 512)
__device__ __align__(16) float d_feats[NTOK][T_TAGS];   // emission scores
__device__ __align__(16) float d_hstate[2][2][B_SZ][H2_DIM]; // [parity][dir][b][h]
// 4 monotonic barrier counters, each on its own 128B line (zero-initialized .bss;
// reset to 0 by viterbi_kernel each call so graph replays are deterministic)
__device__ unsigned int d_cnt[4 * 32];

// ---------- group barrier primitives (release-red arrive, acquire poll) ----
__device__ __forceinline__ void bar_arrive(unsigned int* c) {
    asm volatile("red.release.gpu.global.add.u32 [%0], 1;" :: "l"(c) : "memory");
}
__device__ __forceinline__ unsigned int bar_ld_acq(const unsigned int* c) {
    unsigned int v;
    asm volatile("ld.acquire.gpu.global.u32 %0, [%1];" : "=r"(v) : "l"(c) : "memory");
    return v;
}

// ---------------- input GEMM: G = gather(emb, tok) @ wih^T + bih + bhh -----
// M=16384 (64-tile), N=1024 (64-tile), K=300 (12-tile, 25 iters exact)
// Block (0,0,0) additionally seeds d_hstate[0] from h0 (init kernel folded in).
__global__ __launch_bounds__(256) void input_gemm_kernel(
    const int*   __restrict__ sent,
    const float* __restrict__ emb,
    const float* __restrict__ wih_f, const float* __restrict__ bih_f, const float* __restrict__ bhh_f,
    const float* __restrict__ wih_b, const float* __restrict__ bih_b, const float* __restrict__ bhh_b,
    const float* __restrict__ h0)
{
    const int dir = blockIdx.z;
    const float* wih = dir ? wih_b : wih_f;
    const float* bih = dir ? bih_b : bih_f;
    const float* bhh = dir ? bhh_b : bhh_f;
    float* Gout = &d_G[dir][0][0];

    __shared__ __align__(16) float As[12][64];
    __shared__ __align__(16) float Bs[12][64];
    __shared__ int toks[64];

    const int tid = threadIdx.x;
    const int n0 = blockIdx.x * 64;
    const int j0 = blockIdx.y * 64;

    // folded init: copy h0 -> d_hstate parity 0 (layout (2,B,H2) matches)
    if (blockIdx.x == 0 && blockIdx.y == 0 && blockIdx.z == 0) {
        float* dst = &d_hstate[0][0][0][0];
        for (int i = tid; i < 2 * B_SZ * H2_DIM; i += 256)
            dst[i] = h0[i];
    }

    if (tid < 64) toks[tid] = sent[n0 + tid];
    __syncthreads();

    const int tx = tid & 15;        // j quad
    const int ty = tid >> 4;        // n quad
    ull acc[4][2];                  // [row i][col pair] packed f32x2
#pragma unroll
    for (int i = 0; i < 4; ++i) { acc[i][0] = 0ull; acc[i][1] = 0ull; }

    for (int k0 = 0; k0 < E_DIM; k0 += 12) {
#pragma unroll
        for (int i = 0; i < 3; ++i) {
            int idx = i * 256 + tid;            // 0..767 = 64 rows * 12 k
            int nn = idx / 12, kk = idx % 12;
            As[kk][nn] = emb[(size_t)toks[nn] * E_DIM + k0 + kk];
            Bs[kk][nn] = wih[(size_t)(j0 + nn) * E_DIM + k0 + kk];
        }
        __syncthreads();
#pragma unroll
        for (int kk = 0; kk < 12; ++kk) {
            float4 a = *(const float4*)&As[kk][ty * 4];
            ulonglong2 bv = *(const ulonglong2*)&Bs[kk][tx * 4];
            ull pa0 = pk2(a.x, a.x);
            ull pa1 = pk2(a.y, a.y);
            ull pa2 = pk2(a.z, a.z);
            ull pa3 = pk2(a.w, a.w);
            fma2(acc[0][0], pa0, bv.x); fma2(acc[0][1], pa0, bv.y);
            fma2(acc[1][0], pa1, bv.x); fma2(acc[1][1], pa1, bv.y);
            fma2(acc[2][0], pa2, bv.x); fma2(acc[2][1], pa2, bv.y);
            fma2(acc[3][0], pa3, bv.x); fma2(acc[3][1], pa3, bv.y);
        }
        __syncthreads();
    }

    float4 bi = *(const float4*)&bih[j0 + tx * 4];
    float4 bh = *(const float4*)&bhh[j0 + tx * 4];
    float bs0 = bi.x + bh.x, bs1 = bi.y + bh.y, bs2 = bi.z + bh.z, bs3 = bi.w + bh.w;
#pragma unroll
    for (int ii = 0; ii < 4; ++ii) {
        int n = n0 + ty * 4 + ii;
        float2 lo = up2(acc[ii][0]);
        float2 hi = up2(acc[ii][1]);
        float4 o = make_float4(lo.x + bs0, lo.y + bs1, hi.x + bs2, hi.y + bs3);
        *(float4*)&Gout[(size_t)n * G4 + j0 + tx * 4] = o;
    }
}

// ---------------- persistent bidirectional LSTM -----------------------------
// 128 blocks x 256 threads: dir = bid>>6; slice = bid&63 -> batch half (32 b)
// x hidden seg (8 h-units = 32 gate rows).
// Inner loop: rows pre-paired in Ws4 (natural layout), hidden state staged
// PRE-DUPLICATED (Hdup) so no per-iteration packing: 3 LDS.128 + 4 FFMA2 / 2k.
// 2 warps/SMSP hide LDS latency. Gate-exchange buffer aliases Hdup (smem=48KB).
__global__ __launch_bounds__(256, 1) void lstm_kernel(
    const float* __restrict__ whh_f,
    const float* __restrict__ whh_b,
    const float* __restrict__ c0)
{
    const int dir   = blockIdx.x >> 6;
    const int slice = blockIdx.x & 63;
    const int bh    = slice >> 5;     // 0/1 batch half
    const int hseg  = slice & 31;     // hidden segment (8 units -> 32 gate rows)
    const int bbase = bh * 32;
    const int tid   = threadIdx.x;
    unsigned int* grp_cnt = &d_cnt[(blockIdx.x >> 5) * 32];  // group = dir*2+bh

    // Ws4[k2][rp] = (w[2k2][2rp], w[2k2][2rp+1], w[2k2+1][2rp], w[2k2+1][2rp+1])
    // As ulonglong2: .x = row-pair at even k, .y = row-pair at odd k.
    __shared__ __align__(16) float4 Ws4[128][16];        // 32 KB
    // Hdup[k2][b]: .x = (h[2k2][b], h[2k2][b]), .y = (h[2k2+1][b], h[2k2+1][b])
    __shared__ __align__(16) ulonglong2 Hdup[32][32];    // 16 KB (one 64-k chunk)
    float (*Gsm)[34] = (float(*)[34])&Hdup[0][0];        // aliased gate exchange

    const float* whh = dir ? whh_b : whh_f;
    const float* Gin = &d_G[dir][0][0];

    // Build Ws4 once (2048 float4 entries, 8 per thread)
    for (int i = tid; i < 128 * 16; i += 256) {
        int k2 = i >> 4, rp = i & 15;
        int r0 = 2 * rp, r1 = r0 + 1;
        int rg0 = (r0 >> 3) * H2_DIM + hseg * 8 + (r0 & 7);
        int rg1 = (r1 >> 3) * H2_DIM + hseg * 8 + (r1 & 7);
        Ws4[k2][rp] = make_float4(whh[(size_t)rg0 * H2_DIM + 2 * k2],
                                  whh[(size_t)rg1 * H2_DIM + 2 * k2],
                                  whh[(size_t)rg0 * H2_DIM + 2 * k2 + 1],
                                  whh[(size_t)rg1 * H2_DIM + 2 * k2 + 1]);
    }

    // GEMM ownership: thread -> row pair (2tx, 2tx+1) x batches (2ty, 2ty+1)
    const int tx = tid & 15, ty = tid >> 4;   // ty 0..15
    const int r0 = 2 * tx;
    const int rg0 = (r0 >> 3) * H2_DIM + hseg * 8 + (r0 & 7);  // rg1 = rg0+1 (r0 even)
    const int b0 = 2 * ty;

    // staging ownership: thread -> batch (tid&31), k-octet (tid>>5)*8
    const int stg_b  = tid & 31;
    const int stg_kq = tid >> 5;          // 0..7
    const int kb = stg_kq * 8;            // k offset within a 64-k chunk

    // pointwise ownership: thread -> (b = tid>>3, hh = tid&7)
    const int bq = tid >> 3, hh = tid & 7;
    const int hidx = hseg * 8 + hh;
    float cst = c0[dir * B_SZ * H2_DIM + (bbase + bq) * H2_DIM + hidx];

    // G loads for step 0
    float2 gv0, gv1;
    {
        const int s0 = dir ? (S_LEN - 1) : 0;
        gv0 = *(const float2*)&Gin[(size_t)(s0 * B_SZ + bbase + b0) * G4 + rg0];
        gv1 = *(const float2*)&Gin[(size_t)(s0 * B_SZ + bbase + b0 + 1) * G4 + rg0];
    }

    __syncthreads();

    for (int it = 0; it < S_LEN; ++it) {
        const int s = dir ? (S_LEN - 1 - it) : it;
        const int p = it & 1;
        const float* hprev = &d_hstate[p][dir][0][0];
        float* hnext = &d_hstate[p ^ 1][dir][0][0];
        const float* hp = &hprev[(bbase + stg_b) * H2_DIM];

        // prefetch chunk 0 of hprev (8 consecutive k values)
        float4 pf0 = __ldcg((const float4*)&hp[kb]);
        float4 pf1 = __ldcg((const float4*)&hp[kb + 4]);

        ull a00 = 0ull, a01 = 0ull;   // (g[r0], g[r1]) for batches b0, b0+1

#pragma unroll 1
        for (int c = 0; c < 4; ++c) {
            // store prefetched chunk c into Hdup (pre-duplicated pairs)
            {
                int k2w = kb >> 1;
                Hdup[k2w + 0][stg_b] = make_ulonglong2(pk2(pf0.x, pf0.x), pk2(pf0.y, pf0.y));
                Hdup[k2w + 1][stg_b] = make_ulonglong2(pk2(pf0.z, pf0.z), pk2(pf0.w, pf0.w));
                Hdup[k2w + 2][stg_b] = make_ulonglong2(pk2(pf1.x, pf1.x), pk2(pf1.y, pf1.y));
                Hdup[k2w + 3][stg_b] = make_ulonglong2(pk2(pf1.z, pf1.z), pk2(pf1.w, pf1.w));
            }
            // prefetch chunk c+1 (hidden behind compute)
            if (c < 3) {
                pf0 = __ldcg((const float4*)&hp[(c + 1) * 64 + kb]);
                pf1 = __ldcg((const float4*)&hp[(c + 1) * 64 + kb + 4]);
            }
            __syncthreads();

#pragma unroll 8
            for (int k2l = 0; k2l < 32; ++k2l) {
                ulonglong2 ws = *(const ulonglong2*)&Ws4[c * 32 + k2l][tx];
                ulonglong2 h0 = Hdup[k2l][b0];
                ulonglong2 h1 = Hdup[k2l][b0 + 1];
                fma2(a00, ws.x, h0.x); fma2(a00, ws.y, h0.y);
                fma2(a01, ws.x, h1.x); fma2(a01, ws.y, h1.y);
            }
            __syncthreads();
        }

        // write gates to exchange buffer (aliases Hdup; safe after last sync)
        {
            float2 u0 = up2(a00), u1 = up2(a01);
            Gsm[b0][r0]         = u0.x + gv0.x;
            Gsm[b0][r0 + 1]     = u0.y + gv0.y;
            Gsm[b0 + 1][r0]     = u1.x + gv1.x;
            Gsm[b0 + 1][r0 + 1] = u1.y + gv1.y;
        }
        __syncthreads();

        // pointwise: one (b,h) pair per thread
        {
            float gi = Gsm[bq][hh], gf = Gsm[bq][8 + hh];
            float gg = Gsm[bq][16 + hh], go = Gsm[bq][24 + hh];
            float si = 1.f / (1.f + expf(-gi));
            float sf = 1.f / (1.f + expf(-gf));
            float so = 1.f / (1.f + expf(-go));
            cst = sf * cst + si * tanhf(gg);
            float h = so * tanhf(cst);
            __stcg(&hnext[(bbase + bq) * H2_DIM + hidx], h);
            d_Hout[s * B_SZ + bbase + bq][dir * H2_DIM + hidx] = h;
        }

        if (it < S_LEN - 1) {
            // prefetch next step's G BEFORE the barrier (independent of h)
            const int sn = dir ? (S_LEN - 2 - it) : (it + 1);
            float2 gn0 = *(const float2*)&Gin[(size_t)(sn * B_SZ + bbase + b0) * G4 + rg0];
            float2 gn1 = *(const float2*)&Gin[(size_t)(sn * B_SZ + bbase + b0 + 1) * G4 + rg0];

            // group barrier: release-arrive + acquire-poll on monotonic counter
            __syncthreads();
            if (tid == 0) {
                bar_arrive(grp_cnt);
                const unsigned int target = (unsigned int)(it + 1) * GROUP_BLOCKS;
                while (bar_ld_acq(grp_cnt) < target) { }
            }
            __syncthreads();

            gv0 = gn0; gv1 = gn1;
        }
    }
}

// ---------------- feats: (16384 x 512) @ (512 x 10) + b ---------------------
__global__ __launch_bounds__(256) void feats_kernel(
    const float* __restrict__ W_out, const float* __restrict__ b_out)
{
    const int warp = threadIdx.x >> 5;
    const int lane = threadIdx.x & 31;
    const int n = blockIdx.x * 8 + warp;
    const float4* h4 = (const float4*)&d_Hout[n][0];

    float acc[T_TAGS];
#pragma unroll
    for (int t = 0; t < T_TAGS; ++t) acc[t] = 0.f;

#pragma unroll
    for (int i = 0; i < 4; ++i) {
        int q = i * 32 + lane;               // float4 index (0..127)
        float4 hv = h4[q];
#pragma unroll
        for (int t = 0; t < T_TAGS; ++t) {
            float4 w = *(const float4*)&W_out[t * H_DIM + q * 4];
            acc[t] += hv.x * w.x + hv.y * w.y + hv.z * w.z + hv.w * w.w;
        }
    }
#pragma unroll
    for (int t = 0; t < T_TAGS; ++t) {
        float v = acc[t];
#pragma unroll
        for (int off = 16; off > 0; off >>= 1)
            v += __shfl_down_sync(0xffffffffu, v, off);
        if (lane == 0) d_feats[n][t] = v + b_out[t];
    }
}

// ---------------- Viterbi: one warp per batch --------------------------------
// Also resets the lstm barrier counters (stream-ordered after lstm_kernel).
// Emission row for step s+1 is prefetched before step s's max chain so the
// L2 round-trip is hidden.
__global__ void viterbi_kernel(const float* __restrict__ trans, float* __restrict__ out) {
    const int b = blockIdx.x;
    const int lane = threadIdx.x;
    __shared__ float tr[T_TAGS][T_TAGS];
    __shared__ unsigned char bp[S_LEN][T_TAGS];

    if (b == 0 && lane < 4) d_cnt[lane * 32] = 0u;

    for (int i = lane; i < T_TAGS * T_TAGS; i += 32)
        tr[i / T_TAGS][i % T_TAGS] = trans[i];
    __syncwarp();

    const int ln = lane < T_TAGS ? lane : 0;   // safe index for lanes >= 10
    float fv = (lane == START_TAG) ? 0.f : -10000.f;
    float fcur = d_feats[b * S_LEN][ln];

    for (int s = 0; s < S_LEN; ++s) {
        float fnxt = (s + 1 < S_LEN) ? d_feats[b * S_LEN + s + 1][ln] : 0.f;
        float best = -3.4e38f;
        int arg = 0;
#pragma unroll
        for (int pv = 0; pv < T_TAGS; ++pv) {
            float fp = __shfl_sync(0xffffffffu, fv, pv);
            float v = fp + tr[ln][pv];
            if (v > best) { best = v; arg = pv; }   // strict > keeps FIRST max (jnp.argmax)
        }
        if (lane < T_TAGS) bp[s][lane] = (unsigned char)arg;
        fv = best + fcur;
        fcur = fnxt;
        __syncwarp();
    }

    float term = fv + tr[STOP_TAG][ln];
    __syncwarp();

    float bestv = -3.4e38f;
    int bestt = 0;
#pragma unroll
    for (int t = 0; t < T_TAGS; ++t) {
        float v = __shfl_sync(0xffffffffu, term, t);
        if (v > bestv) { bestv = v; bestt = t; }
    }

    if (lane == 0) {
        out[b] = bestv;                      // path_score (B,1)
        float* pathout = out + B_SZ + b * S_LEN;
        int cur = bestt;
        pathout[S_LEN - 1] = (float)cur;
        for (int s = S_LEN - 2; s >= 0; --s) {
            cur = bp[s + 1][cur];
            pathout[s] = (float)cur;
        }
    }
}

// ---------------- launch ------------------------------------------------------
extern "C" void kernel_launch(void* const* d_in, const int* in_sizes, int n_in,
                              void* d_out, int out_size) {
    const int*   sent  = (const int*)  d_in[0];
    const float* emb   = (const float*)d_in[1];
    const float* wih_f = (const float*)d_in[2];
    const float* whh_f = (const float*)d_in[3];
    const float* bih_f = (const float*)d_in[4];
    const float* bhh_f = (const float*)d_in[5];
    const float* wih_b = (const float*)d_in[6];
    const float* whh_b = (const float*)d_in[7];
    const float* bih_b = (const float*)d_in[8];
    const float* bhh_b = (const float*)d_in[9];
    const float* W_out = (const float*)d_in[10];
    const float* b_out = (const float*)d_in[11];

    // Resolve trailing-argument order at runtime (transitions = 100 elems).
    const float *trans, *h0, *c0;
    if (n_in >= 15 && in_sizes[12] == 100) {
        trans = (const float*)d_in[12];
        h0    = (const float*)d_in[13];
        c0    = (const float*)d_in[14];
    } else {
        h0    = (const float*)d_in[12];
        c0    = (const float*)d_in[13];
        trans = (const float*)d_in[14];
    }

    float* out = (float*)d_out;

    dim3 g(NTOK / 64, G4 / 64, 2);   // 256 x 16 x 2
    input_gemm_kernel<<<g, 256>>>(sent, emb, wih_f, bih_f, bhh_f,
                                  wih_b, bih_b, bhh_b, h0);
    lstm_kernel<<<LSTM_BLOCKS, 256>>>(whh_f, whh_b, c0);
    feats_kernel<<<NTOK / 8, 256>>>(W_out, b_out);
    viterbi_kernel<<<B_SZ, 32>>>(trans, out);
    (void)out_size; (void)n_in;
}